// round 7
// baseline (speedup 1.0000x reference)
#include <cuda_runtime.h>
#include <cstdint>
#include <math.h>

#define BATCH 32768
#define NA 9
#define NR 4
#define LRS 0.2f
#define BN_EPS 1e-5f
#define MTOT (BATCH*NA)
#define TPB 576

// ---- scratch (device globals; no allocs) ----
__device__ float g_h0[(size_t)MTOT*64];
__device__ float g_h1[(size_t)MTOT*128];
__device__ float g_h2[(size_t)MTOT*256];
__device__ float g_wt[256*640];
__device__ float g_stats[3][2][16];

__global__ void zero_stats_kernel() {
    int i = threadIdx.x;
    if (i < 96) ((float*)g_stats)[i] = 0.0f;
}

// ---------------- helpers ----------------
static __device__ __forceinline__ uint32_t s2u(const void* p){
    uint32_t a;
    asm("{ .reg .u64 t; cvta.to.shared.u64 t, %1; cvt.u32.u64 %0, t; }":"=r"(a):"l"(p));
    return a;
}
static __device__ __forceinline__ float tf32r(float v){
    uint32_t u; asm("cvt.rna.tf32.f32 %0, %1;" : "=r"(u) : "f"(v));
    return __uint_as_float(u);
}
#define CPA16(dst,src) asm volatile("cp.async.cg.shared.global [%0], [%1], 16;"::"r"(dst),"l"(src):"memory")
#define CPA_COMMIT()   asm volatile("cp.async.commit_group;":::"memory")
#define CPA_WAIT(n)    asm volatile("cp.async.wait_group %0;"::"n"(n):"memory")

static __device__ __forceinline__ void mma_tf32(
    float& d0, float& d1, float& d2, float& d3,
    uint32_t a0, uint32_t a1, uint32_t a2, uint32_t a3,
    uint32_t b0, uint32_t b1)
{
    asm volatile(
        "mma.sync.aligned.m16n8k8.row.col.f32.tf32.tf32.f32 "
        "{%0,%1,%2,%3}, {%4,%5,%6,%7}, {%8,%9}, {%0,%1,%2,%3};"
        : "+f"(d0), "+f"(d1), "+f"(d2), "+f"(d3)
        : "r"(a0), "r"(a1), "r"(a2), "r"(a3), "r"(b0), "r"(b1));
}

// ---------------- Wt build: frag-packed, per-mat K padded to KPM, tf32-rounded ----
template<int DIN,int DOUT,int KPM>
__global__ void wt_build(const float* __restrict__ ws, const float* __restrict__ wr,
                         float* __restrict__ bp){
    constexpr int KTOT = 5*KPM;
    int i = blockIdx.x*256 + threadIdx.x;
    if (i >= DOUT*KTOT) return;
    int n = i / KTOT, k = i - n*KTOT;
    int mat = k / KPM, kk = k - mat*KPM;
    float v = 0.f;
    if (kk < DIN)
        v = (mat == 0) ? ws[kk*DOUT + n] : wr[(size_t)((mat-1)*DIN + kk)*DOUT + n];
    int kstep = k >> 3;
    int lane = (n & 7)*4 + (k & 3), half = (k >> 2) & 1;
    bp[((size_t)(n >> 3)*(KTOT/8) + kstep)*64 + lane*2 + half] = tf32r(v);
}

// ---------------- fused RGCN block (X never touches gmem) ----------------
// CTA = 16 batches (144 rows). Phases p = kc*5 + mat. Per phase: 1 sync,
// MMA(p), produce A(p+1), cp.async B(p+2) into 3-deep ring, commit.
// h chunks staged via cp.async (ride B groups), BN+LReLU+tf32 in place.
template<int DIN, int KPM, int N, int KC, int SOUT, bool NORM, int SIN, int MINCTA>
__global__ void __launch_bounds__(TPB, MINCTA) rgcn_fused(
    const float* __restrict__ hin,   // [B,9,DIN] raw prev output / atom_feats
    const float* __restrict__ adj,   // [B,4,9,9]
    const float* __restrict__ Bp,    // frag-packed weights
    const float* __restrict__ bias,  // [N]
    const float* __restrict__ gamma, // [9] prev-block BN affine
    const float* __restrict__ beta,  // [9]
    float* __restrict__ hout,        // [B,9,N] raw
    float invp)
{
    constexpr int CPM  = KPM / KC;       // h chunks
    constexpr int NPH  = 5 * CPM;        // phases
    constexpr int KS   = KC / 8;
    constexpr int KTOT = 5 * KPM;
    constexpr int ASTR = KC + 4;
    constexpr int ASZ  = 144 * ASTR;
    constexpr int BSZ  = N * KC;
    constexpr int NT   = N / 16;         // n8 tiles per warp (half N)

    extern __shared__ __align__(16) float sm[];
    float* Hs     = sm;                  // [2][ASZ] normalized h chunks
    float* Ar     = Hs + 2*ASZ;          // [2][ASZ] produced adj-A chunks
    float* Bs     = Ar + 2*ASZ;          // [3][BSZ]
    float* adj_s  = Bs + 3*BSZ;          // 16*4*81
    float* bias_s = adj_s + 5184;        // N
    __shared__ float red[32];
    __shared__ float nrm[32];

    const int tid = threadIdx.x, lane = tid & 31, wid = tid >> 5;
    const int mtile = wid >> 1, nhalf = wid & 1;
    const int bBase = blockIdx.x * 16;
    const size_t rowBase = (size_t)blockIdx.x * 144;

    auto loadB = [&](int ph, int sB){
        int kc = ph / 5, mat = ph - kc*5;
        int kb = mat*(KPM/8) + kc*KS;
        constexpr int NV = N*KC/4;
        for (int i = tid; i < NV; i += TPB){
            int n8 = i / (KS*16), rem = i - n8*(KS*16);
            int ksl = rem >> 4, q = rem & 15;
            const float* src = Bp + ((size_t)n8*(KTOT/8) + kb + ksl)*64 + q*4;
            CPA16(s2u(Bs + sB*BSZ + (n8*KS + ksl)*64 + q*4), src);
        }
    };
    auto stage_h = [&](int kc, int hb){
        constexpr int RV = KC / 4;
        const float* src0 = hin + rowBase*DIN + kc*KC;
        for (int i = tid; i < 144*RV; i += TPB){
            int row = i / RV, q = i - row*RV;
            CPA16(s2u(Hs + hb*ASZ + row*ASTR + q*4), src0 + (size_t)row*DIN + q*4);
        }
    };
    auto normalize = [&](int hb){
        for (int i = tid; i < 144*KC; i += TPB){
            int row = i / KC, col = i - row*KC;
            float* p = Hs + hb*ASZ + row*ASTR + col;
            float v = *p;
            int n = row % NA;
            v = fmaf(v, nrm[n], nrm[16+n]);
            v = v > 0.f ? v : LRS*v;
            *p = tf32r(v);
        }
    };
    auto produce = [&](int r, int hb, int ab){   // Ar[ab] = adj_r @ Hs[hb]
        constexpr int CW = KC / 4;
        int row = tid >> 2, c0 = (tid & 3)*CW;
        int b = row / NA, n = row - b*NA;
        const float* arow = adj_s + ((b*NR + r)*NA + n)*NA;
        const float* hb0  = Hs + hb*ASZ + (b*NA)*ASTR + c0;
        float acc[CW];
        #pragma unroll
        for (int j = 0; j < CW; j++) acc[j] = 0.f;
        #pragma unroll
        for (int m = 0; m < NA; m++){
            float a = arow[m];
            const float* hr = hb0 + m*ASTR;
            #pragma unroll
            for (int j = 0; j < CW; j++) acc[j] = fmaf(a, hr[j], acc[j]);
        }
        float* dst = Ar + ab*ASZ + row*ASTR + c0;
        #pragma unroll
        for (int j = 0; j < CW; j++) dst[j] = tf32r(acc[j]);
    };

    // ---- prologue ----
    if (tid < 32) red[tid] = 0.f;
    if (NORM && tid < NA){
        float s = g_stats[SIN][0][tid], q = g_stats[SIN][1][tid];
        float mean = s*invp, var = q*invp - mean*mean;
        float a = rsqrtf(var + BN_EPS) * gamma[tid];
        nrm[tid] = a; nrm[16+tid] = beta[tid] - mean*a;
    }
    if (NORM) stage_h(0, 0);
    CPA_COMMIT();                           // g0: h0 (empty for block0)
    loadB(0, 0); CPA_COMMIT();              // g1: B(0)
    if (NPH > 1) loadB(1, 1);
    CPA_COMMIT();                           // g2: B(1)

    if (!NORM){                             // block0: stage atoms directly (tiny)
        for (int i = tid; i < 144*KC; i += TPB){
            int row = i / KC, col = i - row*KC;
            float v = (col < DIN) ? tf32r(hin[(rowBase + row)*DIN + col]) : 0.f;
            Hs[row*ASTR + col] = v;
        }
    }
    for (int i = tid; i < N; i += TPB) bias_s[i] = bias[i];
    for (int i = tid; i < 16*NR*81; i += TPB)
        adj_s[i] = adj[(size_t)bBase*NR*81 + i];

    CPA_WAIT(1);                            // h0 + B(0) landed
    __syncthreads();
    if (NORM) normalize(0);

    float cacc[NT][4];
    #pragma unroll
    for (int j = 0; j < NT; j++)
        #pragma unroll
        for (int q = 0; q < 4; q++) cacc[j][q] = 0.f;

    const int r0f = mtile*16 + (lane >> 2);
    const int kf  = lane & 3;

    // ---- phase loop ----
    for (int p = 0; p < NPH; p++){
        int kc = p / 5, mat = p - kc*5;
        CPA_WAIT(1);                        // B(p) group done (uniform: trailing empty commits)
        __syncthreads();                    // publish produce(p)/normalize; guard ring reuse
        const uint32_t* Au = (const uint32_t*)((mat == 0) ? (Hs + (kc&1)*ASZ)
                                                          : (Ar + (p&1)*ASZ));
        const uint2* Bu = (const uint2*)(Bs + (p % 3)*BSZ);
        #pragma unroll
        for (int ks = 0; ks < KS; ks++){
            uint32_t a0 = Au[r0f*ASTR + ks*8 + kf];
            uint32_t a1 = Au[(r0f+8)*ASTR + ks*8 + kf];
            uint32_t a2 = Au[r0f*ASTR + ks*8 + kf + 4];
            uint32_t a3 = Au[(r0f+8)*ASTR + ks*8 + kf + 4];
            #pragma unroll
            for (int j = 0; j < NT; j++){
                int n8 = nhalf*NT + j;
                uint2 bv = Bu[(n8*KS + ks)*32 + lane];
                mma_tf32(cacc[j][0], cacc[j][1], cacc[j][2], cacc[j][3],
                         a0, a1, a2, a3, bv.x, bv.y);
            }
        }
        // produce next phase's A (overlaps tensor drain)
        if (p + 1 < NPH){
            int nkc = (p+1)/5, nmat = (p+1) - nkc*5;
            if (nmat != 0) produce(nmat - 1, nkc & 1, (p+1) & 1);
        }
        if (mat == 1 && kc + 1 < CPM) stage_h(kc + 1, (kc+1) & 1);
        if (NORM && mat == 3 && kc + 1 < CPM) normalize((kc+1) & 1);
        if (p + 2 < NPH) loadB(p + 2, (p+2) % 3);
        CPA_COMMIT();                       // exactly one group per phase
    }

    // ---- epilogue: bias, raw h store, BN stats ----
    #pragma unroll
    for (int half = 0; half < 2; half++){
        int r0 = mtile*16 + (lane >> 2) + half*8;
        size_t grow = rowBase + r0;
        int an = r0 % NA;
        float ssum = 0.f, qsum = 0.f;
        float* op = &hout[grow * N];
        #pragma unroll
        for (int j = 0; j < NT; j++){
            int col = nhalf*(N/2) + j*8 + (lane & 3)*2;
            float v0 = cacc[j][half*2+0] + bias_s[col];
            float v1 = cacc[j][half*2+1] + bias_s[col+1];
            float2 st2; st2.x = v0; st2.y = v1;
            *(float2*)(op + col) = st2;
            ssum += v0 + v1;
            qsum = fmaf(v0, v0, qsum); qsum = fmaf(v1, v1, qsum);
        }
        atomicAdd(&red[an],      ssum);
        atomicAdd(&red[16 + an], qsum);
    }
    __syncthreads();
    if (tid < NA){
        atomicAdd(&g_stats[SOUT][0][tid], red[tid]);
        atomicAdd(&g_stats[SOUT][1][tid], red[16 + tid]);
    }
}

// ---------------- readout: BN + act + masked sum + FC ----------------
__global__ void __launch_bounds__(256) readout_kernel(
    const float* __restrict__ mask, const float* __restrict__ fcw,
    const float* __restrict__ fcb,  const float* __restrict__ gamma,
    const float* __restrict__ beta, float* __restrict__ out, float inv_count)
{
    __shared__ float a_s[NA], c_s[NA], fcs[256];
    int tid = threadIdx.x;
    if (tid < NA){
        float s = g_stats[2][0][tid], q = g_stats[2][1][tid];
        float mean = s*inv_count, var = q*inv_count - mean*mean;
        float a = rsqrtf(var + BN_EPS)*gamma[tid];
        a_s[tid] = a; c_s[tid] = beta[tid] - mean*a;
    }
    fcs[tid] = fcw[tid];
    __syncthreads();
    int lane = tid & 31, w = tid >> 5;
    int b = blockIdx.x*8 + w;
    float accv = 0.f;
    #pragma unroll
    for (int n = 0; n < NA; n++){
        float mk = mask[b*NA + n];
        const float* hp = &g_h2[((size_t)b*NA + n)*256];
        float aa = a_s[n], cc = c_s[n];
        #pragma unroll
        for (int j = 0; j < 8; j++){
            int e = lane + 32*j;
            float v = fmaf(hp[e], aa, cc);
            v = v > 0.f ? v : LRS*v;
            accv = fmaf(v*mk, fcs[e], accv);
        }
    }
    #pragma unroll
    for (int o = 16; o > 0; o >>= 1) accv += __shfl_xor_sync(0xffffffffu, accv, o);
    if (lane == 0) out[b] = accv + fcb[0];
}

extern "C" void kernel_launch(void* const* d_in, const int* in_sizes, int n_in,
                              void* d_out, int out_size)
{
    const float* atom = (const float*)d_in[0];
    const float* adj  = (const float*)d_in[1];
    const float* mask = (const float*)d_in[2];
    const float* ws0=(const float*)d_in[3],  *wr0=(const float*)d_in[4],  *b0=(const float*)d_in[5],  *g0=(const float*)d_in[6],  *be0=(const float*)d_in[7];
    const float* ws1=(const float*)d_in[8],  *wr1=(const float*)d_in[9],  *b1=(const float*)d_in[10], *g1=(const float*)d_in[11], *be1=(const float*)d_in[12];
    const float* ws2=(const float*)d_in[13], *wr2=(const float*)d_in[14], *b2=(const float*)d_in[15], *g2=(const float*)d_in[16], *be2=(const float*)d_in[17];
    const float* fcw=(const float*)d_in[18], *fcb=(const float*)d_in[19];
    float* out = (float*)d_out;

    float *h0,*h1,*h2,*wtb;
    cudaGetSymbolAddress((void**)&h0, g_h0);
    cudaGetSymbolAddress((void**)&h1, g_h1);
    cudaGetSymbolAddress((void**)&h2, g_h2);
    cudaGetSymbolAddress((void**)&wtb, g_wt);

    // dynamic smem (floats): 4*144*(KC+4) + 3*N*KC + 5184 + N
    const int sm0 = (4*144*12 + 3*64*8   + 5184 + 64)  * 4;   //  54,784
    const int sm1 = (4*144*36 + 3*128*32 + 5184 + 128) * 4;   // 153,344
    const int sm2 = (4*144*36 + 3*256*32 + 5184 + 256) * 4;   // 203,008
    cudaFuncSetAttribute((const void*)rgcn_fused<5,8,64,8,0,false,0,2>,
                         cudaFuncAttributeMaxDynamicSharedMemorySize, sm0);
    cudaFuncSetAttribute((const void*)rgcn_fused<64,64,128,32,1,true,0,1>,
                         cudaFuncAttributeMaxDynamicSharedMemorySize, sm1);
    cudaFuncSetAttribute((const void*)rgcn_fused<128,128,256,32,2,true,1,1>,
                         cudaFuncAttributeMaxDynamicSharedMemorySize, sm2);

    const int GRID = MTOT/144;   // 2048

    zero_stats_kernel<<<1,128>>>();

    // block 0: DIN=5 (KPM=8), N=64, KC=8, NPH=5
    wt_build<5,64,8><<<(64*40+255)/256,256>>>(ws0, wr0, wtb);
    rgcn_fused<5,8,64,8,0,false,0,2><<<GRID,TPB,sm0>>>(
        atom, adj, wtb, b0, g0, be0, h0, 0.f);

    // block 1: DIN=64 (KPM=64), N=128, KC=32, NPH=10
    wt_build<64,128,64><<<(128*320+255)/256,256>>>(ws1, wr1, wtb);
    rgcn_fused<64,64,128,32,1,true,0,1><<<GRID,TPB,sm1>>>(
        h0, adj, wtb, b1, g0, be0, h1, 1.f/((float)BATCH*64.f));

    // block 2: DIN=128 (KPM=128), N=256, KC=32, NPH=20
    wt_build<128,256,128><<<(256*640+255)/256,256>>>(ws2, wr2, wtb);
    rgcn_fused<128,128,256,32,2,true,1,1><<<GRID,TPB,sm2>>>(
        h1, adj, wtb, b2, g1, be1, h2, 1.f/((float)BATCH*128.f));

    readout_kernel<<<BATCH/8,256>>>(mask, fcw, fcb, g2, be2, out, 1.f/((float)BATCH*256.f));
}

// round 8
// speedup vs baseline: 1.1711x; 1.1711x over previous
#include <cuda_runtime.h>
#include <cuda_fp16.h>
#include <cstdint>
#include <math.h>

#define BATCH 32768
#define NA 9
#define NR 4
#define LRS 0.2f
#define BN_EPS 1e-5f
#define MTOT (BATCH*NA)

// ---- scratch (device globals; no allocs) ----
__device__ __align__(16) __half g_h0[(size_t)MTOT*64];
__device__ __align__(16) __half g_h1[(size_t)MTOT*128];
__device__ __align__(16) __half g_h2[(size_t)MTOT*256];
__device__ __align__(16) __half g_x [(size_t)MTOT*640];
__device__ __align__(16) __half g_wt[256*640];
__device__ float g_stats[3][2][16];

__global__ void zero_stats_kernel() {
    int i = threadIdx.x;
    if (i < 96) ((float*)g_stats)[i] = 0.0f;
}

// ---------------- helpers ----------------
static __device__ __forceinline__ uint32_t s2u(const void* p){
    uint32_t a;
    asm("{ .reg .u64 t; cvta.to.shared.u64 t, %1; cvt.u32.u64 %0, t; }":"=r"(a):"l"(p));
    return a;
}
#define CPA16(dst,src) asm volatile("cp.async.cg.shared.global [%0], [%1], 16;"::"r"(dst),"l"(src):"memory")
#define CPA_COMMIT()   asm volatile("cp.async.commit_group;":::"memory")
#define CPA_WAIT(n)    asm volatile("cp.async.wait_group %0;"::"n"(n):"memory")

static __device__ __forceinline__ void mma_f16(
    float& d0, float& d1, float& d2, float& d3,
    uint32_t a0, uint32_t a1, uint32_t a2, uint32_t a3,
    uint32_t b0, uint32_t b1)
{
    asm volatile(
        "mma.sync.aligned.m16n8k16.row.col.f32.f16.f16.f32 "
        "{%0,%1,%2,%3}, {%4,%5,%6,%7}, {%8,%9}, {%0,%1,%2,%3};"
        : "+f"(d0), "+f"(d1), "+f"(d2), "+f"(d3)
        : "r"(a0), "r"(a1), "r"(a2), "r"(a3), "r"(b0), "r"(b1));
}

// ---------------- Wt build: k16 frag-packed fp16 ----------------
// (n,k): l=(n%8)*4+(k%8)/2, r=(k%16)/8, h=k%2
// half offset = ((n/8)*(K5P/16) + k/16)*128 + l*4 + r*2 + h
template<int DIN,int DOUT,int K5P>
__global__ void wt_build(const float* __restrict__ ws, const float* __restrict__ wr,
                         __half* __restrict__ bp){
    int i = blockIdx.x*256 + threadIdx.x;
    if (i >= DOUT*K5P) return;
    int n = i / K5P, k = i - n*K5P;
    float v = 0.f;
    if (k < DIN) v = ws[k*DOUT + n];
    else if (k < 5*DIN) {
        int r = (k - DIN) / DIN, kk = (k - DIN) - r*DIN;
        v = wr[(size_t)(r*DIN + kk)*DOUT + n];
    }
    int l = (n & 7)*4 + ((k & 7) >> 1);
    int rg = (k >> 3) & 1, hb = k & 1;
    bp[((size_t)(n >> 3)*(K5P/16) + (k >> 4))*128 + l*4 + rg*2 + hb] = __float2half_rn(v);
}

// ---------------- X build: X = [h_norm | adj_r @ h_norm] (fp16 out) ----------------
template<int DIN, int K5P, bool NORM, int SIN, typename TI>
__global__ void __launch_bounds__(256) x_build(
    const TI* __restrict__ hin, const float* __restrict__ adj,
    const float* __restrict__ gamma, const float* __restrict__ beta,
    __half* __restrict__ Xo, float invp)
{
    constexpr int MB = 8;
    __shared__ float h_s[MB*NA*DIN];
    __shared__ float adj_s[MB*NR*NA*NA];
    __shared__ float nrm[32];
    const int tid = threadIdx.x;
    const size_t mb = (size_t)blockIdx.x * MB;
    if (NORM && tid < NA){
        float s = g_stats[SIN][0][tid], q = g_stats[SIN][1][tid];
        float mean = s*invp, var = q*invp - mean*mean;
        float a = rsqrtf(var + BN_EPS) * gamma[tid];
        nrm[tid] = a; nrm[16+tid] = beta[tid] - mean*a;
    }
    __syncthreads();
    for (int i = tid; i < MB*NA*DIN; i += 256){
        float v = (float)hin[mb*NA*DIN + i];
        if (NORM){
            int n = (i/DIN) % NA;
            v = fmaf(v, nrm[n], nrm[16+n]);
            v = v > 0.f ? v : LRS*v;
        }
        h_s[i] = v;
    }
    for (int i = tid; i < MB*NR*NA*NA; i += 256)
        adj_s[i] = adj[mb*NR*NA*NA + i];
    __syncthreads();
    // write pairs as __half2
    for (int i = tid; i < MB*NA*(K5P/2); i += 256){
        int row = i / (K5P/2), pp = i - row*(K5P/2);
        int m = row / NA, n = row - m*NA;
        float vv[2];
        #pragma unroll
        for (int t = 0; t < 2; t++){
            int col = pp*2 + t;
            float v = 0.f;
            if (col < DIN) v = h_s[row*DIN + col];
            else if (col < 5*DIN){
                int r = (col - DIN) / DIN, d = (col - DIN) - r*DIN;
                const float* ar = &adj_s[((m*NR + r)*NA + n)*NA];
                const float* hc = &h_s[m*NA*DIN + d];
                #pragma unroll
                for (int mm = 0; mm < NA; mm++) v = fmaf(ar[mm], hc[mm*DIN], v);
            }
            vv[t] = v;
        }
        *(__half2*)&Xo[mb*NA*K5P + (size_t)row*K5P + pp*2] = __floats2half2_rn(vv[0], vv[1]);
    }
}

// ---------------- fp16 mma.sync GEMM: hout = X @ Wt^T + bias (+BN stats) ----------------
// CTA: MROWS x N. 8 warps = 4(M) x 2(N). KC=32 per chunk = 2 k16 steps.
template<int N, int NCH, int K5P, int MROWS, int SOUT, int MINCTA>
__global__ void __launch_bounds__(256, MINCTA) gemm_mma(
    const __half* __restrict__ X,    // [M,K5P]
    const __half* __restrict__ Bp,   // frag-packed fp16 weights
    const float* __restrict__ bias,
    __half* __restrict__ hout)       // [M,N]
{
    constexpr int MT_W = MROWS/64;   // m16 tiles per warp
    constexpr int NT   = N/16;       // n8 tiles per warp
    constexpr int ASTR = 40;         // halves per A row (pad)
    constexpr int ASZ  = MROWS*ASTR; // halves per A stage
    constexpr int BSZ  = N*32;       // halves per B stage
    constexpr int SSTG = (NCH > 1) ? 2 : 1;
    extern __shared__ __align__(16) __half smh[];
    __half* As = smh;                // [SSTG][ASZ]
    __half* Bs = smh + SSTG*ASZ;     // [SSTG][BSZ]
    __shared__ float red[32];
    __shared__ float bias_s[N];

    const int tid = threadIdx.x, lane = tid & 31, wid = tid >> 5;
    const int warp_n = wid & 1, warp_m = wid >> 1;
    const int mBase = blockIdx.x * MROWS;

    if (tid < 32) red[tid] = 0.f;
    for (int i = tid; i < N; i += 256) bias_s[i] = bias[i];

    auto loadA = [&](int kc, int s){
        const __half* src = X + (size_t)mBase*K5P + kc*32;
        #pragma unroll
        for (int i = tid; i < MROWS*4; i += 256){
            int row = i >> 2, seg = i & 3;
            CPA16(s2u(As + s*ASZ + row*ASTR + seg*8), src + (size_t)row*K5P + seg*8);
        }
    };
    auto loadB = [&](int kc, int s){
        #pragma unroll
        for (int i = tid; i < N*4; i += 256){
            int n8 = i >> 5, rem = i & 31, ks = rem >> 4, q = rem & 15;
            const __half* src = Bp + ((size_t)n8*(K5P/16) + kc*2 + ks)*128 + q*8;
            CPA16(s2u(Bs + s*BSZ + (n8*2 + ks)*128 + q*8), src);
        }
    };

    loadA(0,0); loadB(0,0); CPA_COMMIT();
    if (NCH > 1){ loadA(1,1); loadB(1,1); CPA_COMMIT(); }

    float cacc[MT_W][NT][4];
    #pragma unroll
    for (int mtw=0; mtw<MT_W; mtw++)
        #pragma unroll
        for (int j=0;j<NT;j++)
            #pragma unroll
            for (int q=0;q<4;q++) cacc[mtw][j][q] = 0.f;

    for (int kc = 0; kc < NCH; kc++){
        const int s = kc & 1;
        if (kc < NCH-1) CPA_WAIT(1); else CPA_WAIT(0);
        __syncthreads();
        const uint32_t* Au = (const uint32_t*)(As + s*ASZ);   // 20 words per row
        const uint32_t* Bu = (const uint32_t*)(Bs + s*BSZ);
        #pragma unroll
        for (int ks = 0; ks < 2; ks++){
            uint32_t a[MT_W][4];
            #pragma unroll
            for (int mtw = 0; mtw < MT_W; mtw++){
                int r0 = (warp_m*MT_W + mtw)*16 + (lane >> 2);
                int kw = ks*8 + (lane & 3);
                a[mtw][0] = Au[r0*20 + kw];
                a[mtw][1] = Au[(r0+8)*20 + kw];
                a[mtw][2] = Au[r0*20 + kw + 4];
                a[mtw][3] = Au[(r0+8)*20 + kw + 4];
            }
            #pragma unroll
            for (int j = 0; j < NT; j++){
                int n8 = warp_n*NT + j;
                uint32_t b0 = Bu[(n8*2 + ks)*64 + lane*2];
                uint32_t b1 = Bu[(n8*2 + ks)*64 + lane*2 + 1];
                #pragma unroll
                for (int mtw = 0; mtw < MT_W; mtw++)
                    mma_f16(cacc[mtw][j][0], cacc[mtw][j][1],
                            cacc[mtw][j][2], cacc[mtw][j][3],
                            a[mtw][0], a[mtw][1], a[mtw][2], a[mtw][3],
                            b0, b1);
            }
        }
        __syncthreads();
        if (kc + 2 < NCH){ loadA(kc+2, s); loadB(kc+2, s); CPA_COMMIT(); }
    }

    // epilogue: bias, fp16 store, BN stats (fp32)
    #pragma unroll
    for (int mtw = 0; mtw < MT_W; mtw++){
        #pragma unroll
        for (int half = 0; half < 2; half++){
            int r0   = (warp_m*MT_W + mtw)*16 + (lane >> 2) + half*8;
            int grow = mBase + r0;
            int an   = grow % NA;
            float ssum = 0.f, qsum = 0.f;
            __half* op = &hout[(size_t)grow*N];
            #pragma unroll
            for (int j = 0; j < NT; j++){
                int col = warp_n*(N/2) + j*8 + (lane & 3)*2;
                float v0 = cacc[mtw][j][half*2+0] + bias_s[col];
                float v1 = cacc[mtw][j][half*2+1] + bias_s[col+1];
                *(__half2*)(op + col) = __floats2half2_rn(v0, v1);
                ssum += v0 + v1;
                qsum = fmaf(v0, v0, qsum); qsum = fmaf(v1, v1, qsum);
            }
            atomicAdd(&red[an],      ssum);
            atomicAdd(&red[16 + an], qsum);
        }
    }
    __syncthreads();
    if (tid < NA){
        atomicAdd(&g_stats[SOUT][0][tid], red[tid]);
        atomicAdd(&g_stats[SOUT][1][tid], red[16 + tid]);
    }
}

// ---------------- readout: BN + act + masked sum + FC ----------------
__global__ void __launch_bounds__(256) readout_kernel(
    const float* __restrict__ mask, const float* __restrict__ fcw,
    const float* __restrict__ fcb,  const float* __restrict__ gamma,
    const float* __restrict__ beta, float* __restrict__ out, float inv_count)
{
    __shared__ float a_s[NA], c_s[NA], fcs[256];
    int tid = threadIdx.x;
    if (tid < NA){
        float s = g_stats[2][0][tid], q = g_stats[2][1][tid];
        float mean = s*inv_count, var = q*inv_count - mean*mean;
        float a = rsqrtf(var + BN_EPS)*gamma[tid];
        a_s[tid] = a; c_s[tid] = beta[tid] - mean*a;
    }
    fcs[tid] = fcw[tid];
    __syncthreads();
    int lane = tid & 31, w = tid >> 5;
    int b = blockIdx.x*8 + w;
    float accv = 0.f;
    #pragma unroll
    for (int n = 0; n < NA; n++){
        float mk = mask[b*NA + n];
        const __half* hp = &g_h2[((size_t)b*NA + n)*256];
        float aa = a_s[n], cc = c_s[n];
        #pragma unroll
        for (int j = 0; j < 8; j++){
            int e = lane + 32*j;
            float v = fmaf(__half2float(hp[e]), aa, cc);
            v = v > 0.f ? v : LRS*v;
            accv = fmaf(v*mk, fcs[e], accv);
        }
    }
    #pragma unroll
    for (int o = 16; o > 0; o >>= 1) accv += __shfl_xor_sync(0xffffffffu, accv, o);
    if (lane == 0) out[b] = accv + fcb[0];
}

extern "C" void kernel_launch(void* const* d_in, const int* in_sizes, int n_in,
                              void* d_out, int out_size)
{
    const float* atom = (const float*)d_in[0];
    const float* adj  = (const float*)d_in[1];
    const float* mask = (const float*)d_in[2];
    const float* ws0=(const float*)d_in[3],  *wr0=(const float*)d_in[4],  *b0=(const float*)d_in[5],  *g0=(const float*)d_in[6],  *be0=(const float*)d_in[7];
    const float* ws1=(const float*)d_in[8],  *wr1=(const float*)d_in[9],  *b1=(const float*)d_in[10], *g1=(const float*)d_in[11], *be1=(const float*)d_in[12];
    const float* ws2=(const float*)d_in[13], *wr2=(const float*)d_in[14], *b2=(const float*)d_in[15], *g2=(const float*)d_in[16], *be2=(const float*)d_in[17];
    const float* fcw=(const float*)d_in[18], *fcb=(const float*)d_in[19];
    float* out = (float*)d_out;

    __half *h0,*h1,*h2,*xb,*wtb;
    cudaGetSymbolAddress((void**)&h0, g_h0);
    cudaGetSymbolAddress((void**)&h1, g_h1);
    cudaGetSymbolAddress((void**)&h2, g_h2);
    cudaGetSymbolAddress((void**)&xb, g_x);
    cudaGetSymbolAddress((void**)&wtb, g_wt);

    // dynamic smem: SSTG*(MROWS*40 + N*32) halves * 2 bytes
    const int sm0 = 1*(128*40 + 64*32)  * 2;   // 14336
    const int sm1 = 2*(128*40 + 128*32) * 2;   // 36864
    const int sm2 = 2*(64*40  + 256*32) * 2;   // 43008
    cudaFuncSetAttribute((const void*)gemm_mma<64,1,32,128,0,3>,
                         cudaFuncAttributeMaxDynamicSharedMemorySize, sm0);
    cudaFuncSetAttribute((const void*)gemm_mma<128,10,320,128,1,3>,
                         cudaFuncAttributeMaxDynamicSharedMemorySize, sm1);
    cudaFuncSetAttribute((const void*)gemm_mma<256,20,640,64,2,3>,
                         cudaFuncAttributeMaxDynamicSharedMemorySize, sm2);

    zero_stats_kernel<<<1,128>>>();

    // block 0: DIN=5, K5P=32, DOUT=64
    wt_build<5,64,32><<<(64*32+255)/256,256>>>(ws0, wr0, wtb);
    x_build<5,32,false,0,float><<<BATCH/8,256>>>(atom, adj, g0, be0, xb, 0.f);
    gemm_mma<64,1,32,128,0,3><<<MTOT/128,256,sm0>>>(xb, wtb, b0, h0);

    // block 1: DIN=64, K5P=320, DOUT=128
    wt_build<64,128,320><<<(128*320+255)/256,256>>>(ws1, wr1, wtb);
    x_build<64,320,true,0,__half><<<BATCH/8,256>>>(h0, adj, g0, be0, xb, 1.f/((float)BATCH*64.f));
    gemm_mma<128,10,320,128,1,3><<<MTOT/128,256,sm1>>>(xb, wtb, b1, h1);

    // block 2: DIN=128, K5P=640, DOUT=256
    wt_build<128,256,640><<<(256*640+255)/256,256>>>(ws2, wr2, wtb);
    x_build<128,640,true,1,__half><<<BATCH/8,256>>>(h1, adj, g1, be1, xb, 1.f/((float)BATCH*128.f));
    gemm_mma<256,20,640,64,2,3><<<MTOT/64,256,sm2>>>(xb, wtb, b2, h2);

    readout_kernel<<<BATCH/8,256>>>(mask, fcw, fcb, g2, be2, out, 1.f/((float)BATCH*256.f));
}